// round 3
// baseline (speedup 1.0000x reference)
#include <cuda_runtime.h>

// CRF forward scan, probability domain (scaled HMM forward), 2 batches/CTA.
//   warps 0-3 -> batch 2*blockIdx.x, warps 4-7 -> batch 2*blockIdx.x+1.
//   Independent named barriers (bar.sync 1 / bar.sync 2, 128 threads) keep the
//   two scans decoupled -> 2 independent dependency chains per SMSP.
//   Inner loop: 32x LDS.128 (as ulonglong2) + 64x fma.rn.f32x2, no pack MOVs.

#define KDIM 128

__device__ __forceinline__ void fma2(unsigned long long& a,
                                     unsigned long long x,
                                     unsigned long long p) {
    asm("fma.rn.f32x2 %0, %1, %2, %0;" : "+l"(a) : "l"(x), "l"(p));
}
__device__ __forceinline__ unsigned long long add2(unsigned long long a,
                                                   unsigned long long b) {
    unsigned long long r;
    asm("add.rn.f32x2 %0, %1, %2;" : "=l"(r) : "l"(a), "l"(b));
    return r;
}
__device__ __forceinline__ unsigned long long pack2(float lo, float hi) {
    unsigned long long r;
    asm("mov.b64 %0, {%1, %2};" : "=l"(r) : "f"(lo), "f"(hi));
    return r;
}

#define GROUP_BAR() asm volatile("bar.sync %0, 128;" :: "r"(sub + 1) : "memory")

__global__ __launch_bounds__(256, 1)
void crf_fwd_kernel(const float* __restrict__ y,
                    const float* __restrict__ mask,
                    const float* __restrict__ trans,
                    float* __restrict__ out,
                    int T, int B) {
    const int tid  = threadIdx.x;
    const int sub  = tid >> 7;           // batch slot within CTA: 0 or 1
    const int i    = tid & (KDIM - 1);   // output state
    const int b    = blockIdx.x * 2 + sub;
    const int lane = i & 31;
    const int warp = i >> 5;             // warp within group (0..3)

    __shared__ __align__(16) float    pbuf[2][2][KDIM];   // [sub][cur][j]
    __shared__ __align__(16) unsigned wmax[2][2][4];      // [sub][cur][warp]
    __shared__ float redf[2][4];
    __shared__ int   len_sh[2];

    if (b >= B) return;

    // ---- one-time: E row = exp(trans[i][:]) packed into 64 f32x2 regs ----
    unsigned long long E2[64];
    {
        const float4* t4 = reinterpret_cast<const float4*>(trans + (size_t)i * KDIM);
        #pragma unroll
        for (int q = 0; q < 32; q++) {
            float4 v = t4[q];
            E2[2*q]   = pack2(expf(v.x), expf(v.y));
            E2[2*q+1] = pack2(expf(v.z), expf(v.w));
        }
    }

    // ---- init state + renorm buffer + sequence length (per group) ----
    if (i == 0) len_sh[sub] = 0;
    pbuf[sub][0][i] = (i == 2) ? 1.0f : 0.0f;        // SOS_IDX = 2
    if (i < 4) wmax[sub][0][i] = 0x3f800000u;        // Z_0 = 1.0
    GROUP_BAR();
    {
        const float* mb = mask + (size_t)b * T;
        int cnt = 0;
        for (int t = i; t < T; t += KDIM) cnt += (mb[t] != 0.0f);
        cnt = __reduce_add_sync(0xffffffffu, cnt);
        if (lane == 0) atomicAdd(&len_sh[sub], cnt);
    }
    GROUP_BAR();
    const int len = len_sh[sub];

    // ---- y prefetch pipeline (3 deep) ----
    const float* yb = y + (size_t)b * T * KDIM + i;
    float ey = 0.0f, y1 = 0.0f, y2 = 0.0f;
    if (len > 0) ey = __expf(yb[0]);
    if (1 < T)   y1 = yb[(size_t)KDIM];
    if (2 < T)   y2 = yb[(size_t)2 * KDIM];

    int cur  = 0;
    int eacc = 0;

    for (int t = 0; t < len; t++) {
        // Z_t from previous step's per-warp maxima (one LDS.128)
        uint4 wm4 = *reinterpret_cast<const uint4*>(wmax[sub][cur]);
        unsigned mbits = max(max(wm4.x, wm4.y), max(wm4.z, wm4.w));
        int Ee   = (int)(mbits >> 23);
        float rz = __uint_as_float((unsigned)(254 - Ee) << 23);  // 2^(127-Ee)
        eacc    += Ee - 127;

        // matvec: q_i = sum_j E[i][j] * s_t[j]
        const ulonglong2* p2 =
            reinterpret_cast<const ulonglong2*>(pbuf[sub][cur]);
        unsigned long long a0=0,a1=0,a2=0,a3=0,a4=0,a5=0,a6=0,a7=0;
        #pragma unroll
        for (int q = 0; q < 8; q++) {
            ulonglong2 v0 = p2[4*q+0];
            ulonglong2 v1 = p2[4*q+1];
            ulonglong2 v2 = p2[4*q+2];
            ulonglong2 v3 = p2[4*q+3];
            fma2(a0, E2[8*q+0], v0.x);
            fma2(a1, E2[8*q+1], v0.y);
            fma2(a2, E2[8*q+2], v1.x);
            fma2(a3, E2[8*q+3], v1.y);
            fma2(a4, E2[8*q+4], v2.x);
            fma2(a5, E2[8*q+5], v2.y);
            fma2(a6, E2[8*q+6], v3.x);
            fma2(a7, E2[8*q+7], v3.y);
        }
        unsigned long long aa = add2(add2(add2(a0,a1), add2(a2,a3)),
                                     add2(add2(a4,a5), add2(a6,a7)));
        float qlo, qhi;
        asm("mov.b64 {%0, %1}, %2;" : "=f"(qlo), "=f"(qhi) : "l"(aa));
        float s = (qlo + qhi) * ey * rz;                 // s >= 0 always

        // per-warp max of new s (positive float bits preserve order)
        unsigned wmv = __reduce_max_sync(0xffffffffu, __float_as_uint(s));
        if (lane == 0) wmax[sub][cur ^ 1][warp] = wmv;
        pbuf[sub][cur ^ 1][i] = s;

        // rotate y pipeline (off critical path)
        ey = __expf(y1);
        y1 = y2;
        int tf = t + 3;
        y2 = (tf < T) ? yb[(size_t)tf * KDIM] : 0.0f;

        GROUP_BAR();
        cur ^= 1;
    }

    // ---- final: out[b] = log(sum_i s[i]) + eacc*ln2 ----
    float e = pbuf[sub][cur][i];
    e += __shfl_xor_sync(0xffffffffu, e, 16);
    e += __shfl_xor_sync(0xffffffffu, e, 8);
    e += __shfl_xor_sync(0xffffffffu, e, 4);
    e += __shfl_xor_sync(0xffffffffu, e, 2);
    e += __shfl_xor_sync(0xffffffffu, e, 1);
    if (lane == 0) redf[sub][warp] = e;
    GROUP_BAR();
    if (i == 0) {
        float tot = (redf[sub][0] + redf[sub][1]) +
                    (redf[sub][2] + redf[sub][3]);
        out[b] = logf(tot) + (float)((double)eacc * 0.6931471805599453);
    }
}

extern "C" void kernel_launch(void* const* d_in, const int* in_sizes, int n_in,
                              void* d_out, int out_size) {
    const float* y     = (const float*)d_in[0];   // (B, T, K) f32
    const float* mask  = (const float*)d_in[1];   // (B, T)    f32
    const float* trans = (const float*)d_in[2];   // (K, K)    f32
    float* out = (float*)d_out;                   // (B,)      f32

    const int B = out_size;                       // 64
    const int T = in_sizes[1] / B;                // 256

    crf_fwd_kernel<<<(B + 1) / 2, 256>>>(y, mask, trans, out, T, B);
}

// round 4
// speedup vs baseline: 1.0104x; 1.0104x over previous
#include <cuda_runtime.h>

// CRF forward scan, probability domain (scaled HMM forward).
//   score_t[i] = log(s_t[i]) + eacc*ln2
//   q_i = sum_j E[i][j] * s_t[j];  s' = q * exp(y_t[i]) * 2^-(Ee-127)
//   E-row split across thread pairs: tid = 2*i + h, each thread holds
//   E2[32] (64 regs) for j in [h*64, h*64+64) -> NO register spills.
//   Halves combined with shfl_xor(1). One __syncthreads per step.
//   Masked (prefix) steps skipped via len = sum(mask).

#define KDIM 128

__device__ __forceinline__ void fma2(unsigned long long& a,
                                     unsigned long long x,
                                     unsigned long long p) {
    asm("fma.rn.f32x2 %0, %1, %2, %0;" : "+l"(a) : "l"(x), "l"(p));
}
__device__ __forceinline__ unsigned long long add2(unsigned long long a,
                                                   unsigned long long b) {
    unsigned long long r;
    asm("add.rn.f32x2 %0, %1, %2;" : "=l"(r) : "l"(a), "l"(b));
    return r;
}
__device__ __forceinline__ unsigned long long pack2(float lo, float hi) {
    unsigned long long r;
    asm("mov.b64 %0, {%1, %2};" : "=l"(r) : "f"(lo), "f"(hi));
    return r;
}

__global__ __launch_bounds__(256, 1)
void crf_fwd_kernel(const float* __restrict__ y,
                    const float* __restrict__ mask,
                    const float* __restrict__ trans,
                    float* __restrict__ out,
                    int T) {
    const int b    = blockIdx.x;
    const int tid  = threadIdx.x;
    const int i    = tid >> 1;          // state 0..127
    const int h    = tid & 1;           // j-half
    const int lane = tid & 31;
    const int warp = tid >> 5;          // 0..7

    __shared__ __align__(16) float    pbuf[2][KDIM];
    __shared__ __align__(16) unsigned wmax[2][8];
    __shared__ float redf[8];
    __shared__ int   len_sh;

    // ---- one-time: half E-row = exp(trans[i][h*64 .. +64)) as 32 f32x2 ----
    unsigned long long E2[32];
    {
        const float4* t4 =
            reinterpret_cast<const float4*>(trans + (size_t)i * KDIM + (h << 6));
        #pragma unroll
        for (int q = 0; q < 16; q++) {
            float4 v = t4[q];
            E2[2*q]   = pack2(expf(v.x), expf(v.y));
            E2[2*q+1] = pack2(expf(v.z), expf(v.w));
        }
    }

    // ---- init state, renorm buffer, length ----
    if (tid == 0) len_sh = 0;
    if (tid < KDIM) pbuf[0][tid] = (tid == 2) ? 1.0f : 0.0f;   // SOS_IDX = 2
    if (tid < 8)    wmax[0][tid] = 0x3f800000u;                // Z_0 = 1.0
    __syncthreads();
    {
        const float* mb = mask + (size_t)b * T;
        int cnt = 0;
        for (int t = tid; t < T; t += 256) cnt += (mb[t] != 0.0f);
        cnt = __reduce_add_sync(0xffffffffu, cnt);
        if (lane == 0) atomicAdd(&len_sh, cnt);
    }
    __syncthreads();
    const int len = len_sh;

    // ---- y prefetch pipeline (3 deep); pair-threads load same element ----
    const float* yb = y + (size_t)b * T * KDIM + i;
    float ey = 0.0f, y1 = 0.0f, y2 = 0.0f;
    if (len > 0) ey = __expf(yb[0]);
    if (1 < T)   y1 = yb[(size_t)KDIM];
    if (2 < T)   y2 = yb[(size_t)2 * KDIM];

    int cur  = 0;
    int eacc = 0;
    float s  = 0.0f;

    for (int t = 0; t < len; t++) {
        // Z_t from previous step's per-warp maxima (two LDS.128)
        uint4 wa = *reinterpret_cast<const uint4*>(&wmax[cur][0]);
        uint4 wb = *reinterpret_cast<const uint4*>(&wmax[cur][4]);
        unsigned mbits = max(max(max(wa.x, wa.y), max(wa.z, wa.w)),
                             max(max(wb.x, wb.y), max(wb.z, wb.w)));
        int Ee   = (int)(mbits >> 23);
        float rz = __uint_as_float((unsigned)(254 - Ee) << 23);  // 2^(127-Ee)
        eacc    += Ee - 127;

        // half matvec: sum over 64 j's (16x LDS.128 + 32x fma.f32x2)
        const ulonglong2* p2 =
            reinterpret_cast<const ulonglong2*>(pbuf[cur] + (h << 6));
        unsigned long long a0=0,a1=0,a2=0,a3=0,a4=0,a5=0,a6=0,a7=0;
        #pragma unroll
        for (int q = 0; q < 4; q++) {
            ulonglong2 v0 = p2[4*q+0];
            ulonglong2 v1 = p2[4*q+1];
            ulonglong2 v2 = p2[4*q+2];
            ulonglong2 v3 = p2[4*q+3];
            fma2(a0, E2[8*q+0], v0.x);
            fma2(a1, E2[8*q+1], v0.y);
            fma2(a2, E2[8*q+2], v1.x);
            fma2(a3, E2[8*q+3], v1.y);
            fma2(a4, E2[8*q+4], v2.x);
            fma2(a5, E2[8*q+5], v2.y);
            fma2(a6, E2[8*q+6], v3.x);
            fma2(a7, E2[8*q+7], v3.y);
        }
        unsigned long long aa = add2(add2(add2(a0,a1), add2(a2,a3)),
                                     add2(add2(a4,a5), add2(a6,a7)));
        float qlo, qhi;
        asm("mov.b64 {%0, %1}, %2;" : "=f"(qlo), "=f"(qhi) : "l"(aa));
        float qh = qlo + qhi;
        qh += __shfl_xor_sync(0xffffffffu, qh, 1);   // combine j-halves
        s = qh * ey * rz;                            // s >= 0 always

        // per-warp max of new s (16 distinct states, duplicated; order-safe)
        unsigned wmv = __reduce_max_sync(0xffffffffu, __float_as_uint(s));
        if (lane == 0) wmax[cur ^ 1][warp] = wmv;
        if (h == 0)    pbuf[cur ^ 1][i] = s;

        // rotate y pipeline (off critical path)
        ey = __expf(y1);
        y1 = y2;
        int tf = t + 3;
        y2 = (tf < T) ? yb[(size_t)tf * KDIM] : 0.0f;

        __syncthreads();
        cur ^= 1;
    }

    // ---- final: out[b] = log(sum_i s_i) + eacc*ln2 ----
    // Each warp holds 16 states duplicated x2 -> warp sum = 2 * true sum.
    float e = pbuf[cur][i];
    e += __shfl_xor_sync(0xffffffffu, e, 16);
    e += __shfl_xor_sync(0xffffffffu, e, 8);
    e += __shfl_xor_sync(0xffffffffu, e, 4);
    e += __shfl_xor_sync(0xffffffffu, e, 2);
    e += __shfl_xor_sync(0xffffffffu, e, 1);
    if (lane == 0) redf[warp] = e;
    __syncthreads();
    if (tid == 0) {
        float tot = ((redf[0] + redf[1]) + (redf[2] + redf[3])) +
                    ((redf[4] + redf[5]) + (redf[6] + redf[7]));
        tot *= 0.5f;    // undo duplication
        out[b] = logf(tot) + (float)((double)eacc * 0.6931471805599453);
    }
}

extern "C" void kernel_launch(void* const* d_in, const int* in_sizes, int n_in,
                              void* d_out, int out_size) {
    const float* y     = (const float*)d_in[0];   // (B, T, K) f32
    const float* mask  = (const float*)d_in[1];   // (B, T)    f32
    const float* trans = (const float*)d_in[2];   // (K, K)    f32
    float* out = (float*)d_out;                   // (B,)      f32

    const int B = out_size;                       // 64
    const int T = in_sizes[1] / B;                // 256

    crf_fwd_kernel<<<B, 256>>>(y, mask, trans, out, T);
}